// round 5
// baseline (speedup 1.0000x reference)
#include <cuda_runtime.h>
#include <cstdint>

// Problem constants (match reference)
#define NUM_EXPERTS 64
#define TOP_K 4
#define EMA_DECAY 0.99f

// Ordered-pair histogram scratch: P[a*64+b] counts over tokens of pairs
// (k1<k2) with a = idx[k1], b = idx[k2]. Symmetric coact = P + P^T.
// __device__ global (no allocation allowed anywhere).
__device__ unsigned int g_P[NUM_EXPERTS * NUM_EXPERTS];

// ---------------------------------------------------------------------------
// Kernel 1: zero the scratch (every launch -> deterministic, graph-replayable)
// ---------------------------------------------------------------------------
__global__ void zero_scratch_kernel() {
    int i = blockIdx.x * blockDim.x + threadIdx.x;
    if (i < NUM_EXPERTS * NUM_EXPERTS) g_P[i] = 0u;
}

// ---------------------------------------------------------------------------
// Kernel 2: per-CTA shared-memory pair histogram, then flush to g_P.
// Indices are int32 [N,4] row-major (JAX x64-disabled downgrades int64->int32)
// -> 16 bytes/token -> ONE int4 vector load per token, fully coalesced.
// ---------------------------------------------------------------------------
__global__ void __launch_bounds__(512, 2)
pair_hist_kernel(const int4* __restrict__ idx, unsigned ntok) {
    __shared__ unsigned int sP[NUM_EXPERTS * NUM_EXPERTS];

    for (int i = threadIdx.x; i < NUM_EXPERTS * NUM_EXPERTS; i += blockDim.x)
        sP[i] = 0u;
    __syncthreads();

    const unsigned stride = gridDim.x * blockDim.x;
    for (unsigned t = blockIdx.x * blockDim.x + threadIdx.x; t < ntok; t += stride) {
        int4 v = idx[t];                     // token t's 4 expert ids (0..63)
        unsigned e0 = (unsigned)v.x;
        unsigned e1 = (unsigned)v.y;
        unsigned e2 = (unsigned)v.z;
        unsigned e3 = (unsigned)v.w;

        // 6 ordered slot pairs (k1 < k2)
        atomicAdd(&sP[(e0 << 6) + e1], 1u);
        atomicAdd(&sP[(e0 << 6) + e2], 1u);
        atomicAdd(&sP[(e0 << 6) + e3], 1u);
        atomicAdd(&sP[(e1 << 6) + e2], 1u);
        atomicAdd(&sP[(e1 << 6) + e3], 1u);
        atomicAdd(&sP[(e2 << 6) + e3], 1u);
    }
    __syncthreads();

    for (int i = threadIdx.x; i < NUM_EXPERTS * NUM_EXPERTS; i += blockDim.x) {
        unsigned v = sP[i];
        if (v) atomicAdd(&g_P[i], v);
    }
}

// ---------------------------------------------------------------------------
// Kernel 3: finalize.
//   out[0:64)       = new_load_ema = ema_in * 0.99 + (count/N) * 0.01
//                     where 3*count[e] = rowsum(P)[e] + colsum(P)[e]
//                     (each occurrence of e joins exactly K-1 = 3 pairs)
//   out[64:64+4096) = coact_in + P + P^T
// All accumulants are integers < 2^24 -> fp32-exact -> deterministic.
// ---------------------------------------------------------------------------
__global__ void finalize_kernel(const float* __restrict__ ema_in,
                                const float* __restrict__ coact_in,
                                float* __restrict__ out, unsigned ntok) {
    int i = blockIdx.x * blockDim.x + threadIdx.x;
    if (i < NUM_EXPERTS * NUM_EXPERTS) {
        int a = i >> 6;
        int b = i & 63;
        float sym = (float)(g_P[(a << 6) + b] + g_P[(b << 6) + a]);
        out[NUM_EXPERTS + i] = coact_in[i] + sym;
    }
    if (i < NUM_EXPERTS) {
        unsigned s = 0u;
        #pragma unroll
        for (int j = 0; j < NUM_EXPERTS; j++) {
            s += g_P[(i << 6) + j];
            s += g_P[(j << 6) + i];
        }
        float count = (float)(s / 3u);       // exactly divisible by 3
        float load = count / (float)ntok;
        out[i] = ema_in[i] * EMA_DECAY + load * (1.0f - EMA_DECAY);
    }
}

// ---------------------------------------------------------------------------
// kernel_launch: 3 launches, stream-ordered, graph-capturable, alloc-free.
// Inputs (metadata order):
//   d_in[0] expert_indices        int32  [N,4]   (JAX default x64-off)
//   d_in[1] expert_weights        f32    [N,4]   (UNUSED by reference)
//   d_in[2] expert_load_ema       f32    [64]
//   d_in[3] expert_pair_coact     f32    [64,64]
// Output: f32 [64 + 4096] = (new_load_ema, new_coact) concatenated.
// ---------------------------------------------------------------------------
extern "C" void kernel_launch(void* const* d_in, const int* in_sizes, int n_in,
                              void* d_out, int out_size) {
    const int4* idx       = (const int4*)d_in[0];
    const float* ema_in   = (const float*)d_in[2];
    const float* coact_in = (const float*)d_in[3];
    float* out = (float*)d_out;

    unsigned ntok = (unsigned)(in_sizes[0] / TOP_K);

    zero_scratch_kernel<<<4, 1024>>>();

    // 512 threads/CTA, 2 CTAs/SM target on 148/152-SM parts. 16KB smem/CTA.
    pair_hist_kernel<<<304, 512>>>(idx, ntok);

    finalize_kernel<<<4, 1024>>>(ema_in, coact_in, out, ntok);
}